// round 1
// baseline (speedup 1.0000x reference)
#include <cuda_runtime.h>
#include <math.h>
#include <stdint.h>

// ---------------------------------------------------------------------------
// Static device scratch (allocation-free rule). All sizes in floats.
// Activations live in (B, E, C) layout: x[(b*E + e)*C + c].
// ---------------------------------------------------------------------------
__device__ float  g_bufA[8388608];   // 2*32768*128 max  (x ping)
__device__ float  g_bufB[8388608];   // x pong
__device__ float  g_bufU[4194304];   // up-conv outputs (B, E_i, Cout)
__device__ float  g_bufY[8388608];   // x1 after unpool+skip / final conv outs
__device__ float  g_wt[400000];      // transposed weights, [K=Cin*5][Cout]
__device__ double g_stats[512];      // per-(b,c) sum / sumsq (max 2*128*2)

// ---------------------------------------------------------------------------
// Weight transpose: W (Cout, Cin, 5) -> Wt[k][o], k = c*5+s
// ---------------------------------------------------------------------------
__global__ void wtrans(const float* __restrict__ W, float* __restrict__ Wt,
                       int K, int Cout) {
    int i = blockIdx.x * 256 + threadIdx.x;
    if (i < K * Cout) {
        int k = i / Cout, o = i % Cout;
        Wt[i] = W[(size_t)o * K + k];
    }
}

// ---------------------------------------------------------------------------
// fe (B, C, E) -> (B, E, C) tiled transpose
// ---------------------------------------------------------------------------
__global__ void xpose(const float* __restrict__ in, float* __restrict__ outT,
                      int E, int C) {
    __shared__ float tile[32][33];
    int b = blockIdx.z;
    int e0 = blockIdx.x * 32, c0 = blockIdx.y * 32;
    int tx = threadIdx.x, ty = threadIdx.y;          // (32, 8)
    const float* inb = in + (size_t)b * C * E;
    float* ob = outT + (size_t)b * E * C;
#pragma unroll
    for (int j = 0; j < 32; j += 8)
        tile[ty + j][tx] = inb[(size_t)(c0 + ty + j) * E + e0 + tx];
    __syncthreads();
#pragma unroll
    for (int j = 0; j < 32; j += 8)
        ob[(size_t)(e0 + ty + j) * C + c0 + tx] = tile[tx][ty + j];
}

// ---------------------------------------------------------------------------
// Tiled mesh-conv GEMM.  out[b,e,o] = sum_{c,s} G[e, c*5+s] * Wt[c*5+s, o] + bias[o]
// BE=64 edges/block, CK=8 channel chunk, 256 threads = 16(edge) x 16(out) grid,
// each thread computes a 4 x TO microtile.  Requires COUT == 16*TO.
// ---------------------------------------------------------------------------
template<int CIN, int COUT, int TO>
__global__ __launch_bounds__(256) void conv_tiled(
    const float* __restrict__ x, const int4* __restrict__ gemm,
    const float* __restrict__ Wt, const float* __restrict__ bias,
    float* __restrict__ out, int E)
{
    constexpr int BE = 64, CK = 8, K5 = CK * 5, BEp = 68;
    __shared__ __align__(16) float sG[K5][BEp];
    __shared__ __align__(16) float sW[K5][COUT];
    __shared__ int4 sIdx[BE];

    const int tid = threadIdx.x;
    const int b = blockIdx.y;
    const int e0 = blockIdx.x * BE;
    const float* xb = x + (size_t)b * E * CIN;

    if (tid < BE) sIdx[tid] = gemm[e0 + tid];

    const int tx = tid & 15, ty = tid >> 4;
    float acc[4][TO];
#pragma unroll
    for (int j = 0; j < TO; j++) {
        float bj = bias[ty * TO + j];
#pragma unroll
        for (int i = 0; i < 4; i++) acc[i][j] = bj;
    }

    for (int c0 = 0; c0 < CIN; c0 += CK) {
        __syncthreads();   // protects sG/sW from previous compute (and sIdx 1st iter)
        // stage W chunk (contiguous, coalesced)
        const float* wsrc = Wt + (size_t)c0 * 5 * COUT;
        for (int i = tid; i < K5 * COUT; i += 256)
            (&sW[0][0])[i] = wsrc[i];
        // build G tile: 64 edges x 8 channels, 5 gathered rows each (rows contiguous in C)
        for (int p = tid; p < BE * CK; p += 256) {
            int cc = p & 7;
            int el = p >> 3;
            int c  = c0 + cc;
            int4 n = sIdx[el];
            float xe = xb[(size_t)(e0 + el) * CIN + c];
            float f1 = xb[(size_t)n.x * CIN + c];
            float f2 = xb[(size_t)n.y * CIN + c];
            float f3 = xb[(size_t)n.z * CIN + c];
            float f4 = xb[(size_t)n.w * CIN + c];
            int kb = cc * 5;
            sG[kb + 0][el] = xe;
            sG[kb + 1][el] = f1 + f3;
            sG[kb + 2][el] = f2 + f4;
            sG[kb + 3][el] = fabsf(f1 - f3);
            sG[kb + 4][el] = fabsf(f2 - f4);
        }
        __syncthreads();
#pragma unroll 5
        for (int k = 0; k < K5; k++) {
            const float4 a = *reinterpret_cast<const float4*>(&sG[k][tx * 4]);
            float bv[TO];
            if constexpr (TO == 8) {
                float4 u0 = *reinterpret_cast<const float4*>(&sW[k][ty * 8]);
                float4 u1 = *reinterpret_cast<const float4*>(&sW[k][ty * 8 + 4]);
                bv[0]=u0.x; bv[1]=u0.y; bv[2]=u0.z; bv[3]=u0.w;
                bv[4]=u1.x; bv[5]=u1.y; bv[6]=u1.z; bv[7]=u1.w;
            } else if constexpr (TO == 4) {
                float4 u0 = *reinterpret_cast<const float4*>(&sW[k][ty * 4]);
                bv[0]=u0.x; bv[1]=u0.y; bv[2]=u0.z; bv[3]=u0.w;
            } else {
                float2 u0 = *reinterpret_cast<const float2*>(&sW[k][ty * 2]);
                bv[0]=u0.x; bv[1]=u0.y;
            }
            float av[4] = {a.x, a.y, a.z, a.w};
#pragma unroll
            for (int i = 0; i < 4; i++)
#pragma unroll
                for (int j = 0; j < TO; j++)
                    acc[i][j] = fmaf(av[i], bv[j], acc[i][j]);
        }
    }
#pragma unroll
    for (int i = 0; i < 4; i++) {
        float* po = out + ((size_t)b * E + (e0 + tx * 4 + i)) * COUT + ty * TO;
        if constexpr (TO == 8) {
            *reinterpret_cast<float4*>(po)     = make_float4(acc[i][0], acc[i][1], acc[i][2], acc[i][3]);
            *reinterpret_cast<float4*>(po + 4) = make_float4(acc[i][4], acc[i][5], acc[i][6], acc[i][7]);
        } else if constexpr (TO == 4) {
            *reinterpret_cast<float4*>(po)     = make_float4(acc[i][0], acc[i][1], acc[i][2], acc[i][3]);
        } else {
            *reinterpret_cast<float2*>(po)     = make_float2(acc[i][0], acc[i][1]);
        }
    }
}

// ---------------------------------------------------------------------------
// Small-Cout mesh-conv (COUT = 8): one thread per edge, vectorized row loads.
// ---------------------------------------------------------------------------
template<int CIN>
__global__ __launch_bounds__(256) void conv_small(
    const float* __restrict__ x, const int4* __restrict__ gemm,
    const float* __restrict__ Wt, const float* __restrict__ bias,
    float* __restrict__ out, int E)
{
    constexpr int K = CIN * 5;
    __shared__ float sW[K * 8];
    int tid = threadIdx.x;
    for (int i = tid; i < K * 8; i += 256) sW[i] = Wt[i];
    float acc[8];
#pragma unroll
    for (int o = 0; o < 8; o++) acc[o] = bias[o];
    __syncthreads();

    int b = blockIdx.y;
    int e = blockIdx.x * 256 + tid;
    int4 n = gemm[e];
    const float* xb = x + (size_t)b * E * CIN;
    const float4* r0 = reinterpret_cast<const float4*>(xb + (size_t)e * CIN);
    const float4* r1 = reinterpret_cast<const float4*>(xb + (size_t)n.x * CIN);
    const float4* r2 = reinterpret_cast<const float4*>(xb + (size_t)n.y * CIN);
    const float4* r3 = reinterpret_cast<const float4*>(xb + (size_t)n.z * CIN);
    const float4* r4 = reinterpret_cast<const float4*>(xb + (size_t)n.w * CIN);

#pragma unroll 2
    for (int c4 = 0; c4 < CIN / 4; c4++) {
        float4 xe = r0[c4], a1 = r1[c4], a2 = r2[c4], a3 = r3[c4], a4 = r4[c4];
#define PROC(COMP, CC)                                                         \
        {                                                                      \
            float g0 = xe.COMP;                                                \
            float s1 = a1.COMP + a3.COMP;                                      \
            float s2 = a2.COMP + a4.COMP;                                      \
            float d1 = fabsf(a1.COMP - a3.COMP);                               \
            float d2 = fabsf(a2.COMP - a4.COMP);                               \
            const float* w = &sW[(c4 * 4 + CC) * 5 * 8];                       \
            for (int o = 0; o < 8; o++)                                        \
                acc[o] += g0 * w[o] + s1 * w[8 + o] + s2 * w[16 + o]           \
                        + d1 * w[24 + o] + d2 * w[32 + o];                     \
        }
        PROC(x, 0) PROC(y, 1) PROC(z, 2) PROC(w, 3)
#undef PROC
    }
    float* po = out + ((size_t)b * E + e) * 8;
    *reinterpret_cast<float4*>(po)     = make_float4(acc[0], acc[1], acc[2], acc[3]);
    *reinterpret_cast<float4*>(po + 4) = make_float4(acc[4], acc[5], acc[6], acc[7]);
}

// ---------------------------------------------------------------------------
// unpool + skip: out[b,e,c] = up[b, unpool[e], c] + skip[b,c,e]
// skip read coalesced along E, transposed through smem.
// ---------------------------------------------------------------------------
template<int C>
__global__ __launch_bounds__(256) void unpool_skip(
    const float* __restrict__ up, const int* __restrict__ unpool,
    const float* __restrict__ skip, float* __restrict__ out,
    int Eout, int Ein)
{
    constexpr int TE = 32;
    __shared__ float ssk[C][TE + 1];
    __shared__ int su[TE];
    int tid = threadIdx.x;
    int b = blockIdx.y;
    int e0 = blockIdx.x * TE;
    if (tid < TE) su[tid] = unpool[e0 + tid];
    const float* skb = skip + (size_t)b * C * Eout;
    for (int i = tid; i < C * TE; i += 256) {
        int c = i >> 5, e = i & 31;
        ssk[c][e] = skb[(size_t)c * Eout + e0 + e];
    }
    __syncthreads();
    const float* upb = up + (size_t)b * Ein * C;
    float* ob = out + ((size_t)b * Eout + e0) * C;
    for (int i = tid; i < C * TE; i += 256) {
        int el = i / C, c = i % C;
        ob[(size_t)el * C + c] = upb[(size_t)su[el] * C + c] + ssk[c][el];
    }
}

// ---------------------------------------------------------------------------
// Instance norm: split partial reduction (fp32 partials -> fp64 atomics),
// then elementwise normalize + relu.
// ---------------------------------------------------------------------------
__global__ void zero_stats(double* s) {
    s[threadIdx.x] = 0.0;
    s[threadIdx.x + 256] = 0.0;
}

template<int C, int CG, int CHUNK>
__global__ __launch_bounds__(256) void inorm_partial(
    const float* __restrict__ x, int E, double* __restrict__ stats)
{
    constexpr int LANES = 256 / CG;
    __shared__ float rs[256], rs2[256];
    int tid = threadIdx.x;
    int cl = tid % CG, lane = tid / CG;
    int b = blockIdx.z;
    int c = blockIdx.y * CG + cl;
    int e0 = blockIdx.x * CHUNK;
    const float* xb = x + (size_t)b * E * C;
    float s = 0.f, s2 = 0.f;
    for (int e = e0 + lane; e < e0 + CHUNK; e += LANES) {
        float v = xb[(size_t)e * C + c];
        s += v; s2 += v * v;
    }
    rs[tid] = s; rs2[tid] = s2;
    __syncthreads();
    for (int st = 128; st >= CG; st >>= 1) {
        if (tid < st) { rs[tid] += rs[tid + st]; rs2[tid] += rs2[tid + st]; }
        __syncthreads();
    }
    if (tid < CG) {
        int cc = blockIdx.y * CG + tid;
        atomicAdd(&stats[(b * C + cc) * 2],     (double)rs[tid]);
        atomicAdd(&stats[(b * C + cc) * 2 + 1], (double)rs2[tid]);
    }
}

template<int C>
__global__ __launch_bounds__(256) void inorm_apply(
    float* __restrict__ x, int E, const double* __restrict__ stats)
{
    int idx = blockIdx.x * 256 + threadIdx.x;   // (b*E+e)*C + c
    int c = idx % C;
    int be = idx / C;
    int b = be / E;
    double s  = stats[(b * C + c) * 2];
    double s2 = stats[(b * C + c) * 2 + 1];
    double m = s / E;
    double var = s2 / E - m * m;
    float r = rsqrtf((float)var + 1e-5f);
    float v = (x[idx] - (float)m) * r;
    x[idx] = v > 0.f ? v : 0.f;
}

// Final norm: reads (B,E,8), writes d_out in (B,8,E) with relu.
__global__ __launch_bounds__(256) void inorm_apply_final(
    const float* __restrict__ x, int E, const double* __restrict__ stats,
    float* __restrict__ out)
{
    int idx = blockIdx.x * 256 + threadIdx.x;   // output layout (b*8+c)*E + e
    int e = idx % E;
    int t = idx / E;
    int c = t % 8;
    int b = t / 8;
    double s  = stats[(b * 8 + c) * 2];
    double s2 = stats[(b * 8 + c) * 2 + 1];
    double m = s / E;
    double var = s2 / E - m * m;
    float r = rsqrtf((float)var + 1e-5f);
    float v = (x[((size_t)b * E + e) * 8 + c] - (float)m) * r;
    out[idx] = v > 0.f ? v : 0.f;
}

// ---------------------------------------------------------------------------
// Host driver (graph-capturable: kernel launches only).
// ---------------------------------------------------------------------------
extern "C" void kernel_launch(void* const* d_in, const int* in_sizes, int n_in,
                              void* d_out, int out_size)
{
    (void)in_sizes; (void)n_in; (void)out_size;
    const int E0 = 16384, E1 = 32768, E2 = 65536, E3 = 131072;

    const float* fe    = (const float*)d_in[0];
    const float* skip0 = (const float*)d_in[1];
    const float* skip1 = (const float*)d_in[2];
    const float* skip2 = (const float*)d_in[3];
    const int4*  gm0   = (const int4*)d_in[4];
    const int4*  gm1   = (const int4*)d_in[5];
    const int4*  gm2   = (const int4*)d_in[6];
    const int4*  gm3   = (const int4*)d_in[7];
    const int*   up0   = (const int*)d_in[8];
    const int*   up1   = (const int*)d_in[9];
    const int*   up2   = (const int*)d_in[10];
    const float* Wup0 = (const float*)d_in[11]; const float* bup0 = (const float*)d_in[12];
    const float* Wc0  = (const float*)d_in[13]; const float* bc0  = (const float*)d_in[14];
    const float* Wup1 = (const float*)d_in[15]; const float* bup1 = (const float*)d_in[16];
    const float* Wc1  = (const float*)d_in[17]; const float* bc1  = (const float*)d_in[18];
    const float* Wup2 = (const float*)d_in[19]; const float* bup2 = (const float*)d_in[20];
    const float* Wc2  = (const float*)d_in[21]; const float* bc2  = (const float*)d_in[22];
    const float* Wupf = (const float*)d_in[23]; const float* bupf = (const float*)d_in[24];
    const float* Wcf  = (const float*)d_in[25]; const float* bcf  = (const float*)d_in[26];
    float* outp = (float*)d_out;

    float *bufA, *bufB, *bufU, *bufY, *wt; double* stats;
    cudaGetSymbolAddress((void**)&bufA, g_bufA);
    cudaGetSymbolAddress((void**)&bufB, g_bufB);
    cudaGetSymbolAddress((void**)&bufU, g_bufU);
    cudaGetSymbolAddress((void**)&bufY, g_bufY);
    cudaGetSymbolAddress((void**)&wt,   g_wt);
    cudaGetSymbolAddress((void**)&stats, g_stats);

    // transposed weight offsets
    float* Wt_up0 = wt;                 // 256*5*128 = 163840
    float* Wt_c0  = wt + 163840;        // 128*5*128 =  81920
    float* Wt_up1 = wt + 245760;        // 128*5*64  =  40960
    float* Wt_c1  = wt + 286720;        //  64*5*64  =  20480
    float* Wt_up2 = wt + 307200;        //  64*5*32  =  10240
    float* Wt_c2  = wt + 317440;        //  32*5*32  =   5120
    float* Wt_upf = wt + 322560;        //  32*5*8   =   1280
    float* Wt_cf  = wt + 323840;        //   8*5*8   =    320

    auto wtl = [](const float* W, float* dst, int K, int Cout) {
        int ne = K * Cout;
        wtrans<<<(ne + 255) / 256, 256>>>(W, dst, K, Cout);
    };
    wtl(Wup0, Wt_up0, 256 * 5, 128);
    wtl(Wc0,  Wt_c0,  128 * 5, 128);
    wtl(Wup1, Wt_up1, 128 * 5,  64);
    wtl(Wc1,  Wt_c1,   64 * 5,  64);
    wtl(Wup2, Wt_up2,  64 * 5,  32);
    wtl(Wc2,  Wt_c2,   32 * 5,  32);
    wtl(Wupf, Wt_upf,  32 * 5,   8);
    wtl(Wcf,  Wt_cf,    8 * 5,   8);

    // fe (2,256,16384) -> bufA (2,16384,256)
    xpose<<<dim3(E0 / 32, 256 / 32, 2), dim3(32, 8)>>>(fe, bufA, E0, 256);

    // ---- Level 0 ----
    conv_tiled<256, 128, 8><<<dim3(E0 / 64, 2), 256>>>(bufA, gm0, Wt_up0, bup0, bufU, E0);
    unpool_skip<128><<<dim3(E1 / 32, 2), 256>>>(bufU, up0, skip0, bufY, E1, E0);
    conv_tiled<128, 128, 8><<<dim3(E1 / 64, 2), 256>>>(bufY, gm1, Wt_c0, bc0, bufB, E1);
    zero_stats<<<1, 256>>>(stats);
    inorm_partial<128, 32, 2048><<<dim3(E1 / 2048, 4, 2), 256>>>(bufB, E1, stats);
    inorm_apply<128><<<(2 * E1 * 128) / 256, 256>>>(bufB, E1, stats);

    // ---- Level 1 ----
    conv_tiled<128, 64, 4><<<dim3(E1 / 64, 2), 256>>>(bufB, gm1, Wt_up1, bup1, bufU, E1);
    unpool_skip<64><<<dim3(E2 / 32, 2), 256>>>(bufU, up1, skip1, bufY, E2, E1);
    conv_tiled<64, 64, 4><<<dim3(E2 / 64, 2), 256>>>(bufY, gm2, Wt_c1, bc1, bufA, E2);
    zero_stats<<<1, 256>>>(stats);
    inorm_partial<64, 32, 2048><<<dim3(E2 / 2048, 2, 2), 256>>>(bufA, E2, stats);
    inorm_apply<64><<<(2 * E2 * 64) / 256, 256>>>(bufA, E2, stats);

    // ---- Level 2 ----
    conv_tiled<64, 32, 2><<<dim3(E2 / 64, 2), 256>>>(bufA, gm2, Wt_up2, bup2, bufU, E2);
    unpool_skip<32><<<dim3(E3 / 32, 2), 256>>>(bufU, up2, skip2, bufY, E3, E2);
    conv_tiled<32, 32, 2><<<dim3(E3 / 64, 2), 256>>>(bufY, gm3, Wt_c2, bc2, bufB, E3);
    zero_stats<<<1, 256>>>(stats);
    inorm_partial<32, 32, 2048><<<dim3(E3 / 2048, 1, 2), 256>>>(bufB, E3, stats);
    inorm_apply<32><<<(2 * E3 * 32) / 256, 256>>>(bufB, E3, stats);

    // ---- Final ----
    conv_small<32><<<dim3(E3 / 256, 2), 256>>>(bufB, gm3, Wt_upf, bupf, bufU, E3);
    conv_small<8><<<dim3(E3 / 256, 2), 256>>>(bufU, gm3, Wt_cf, bcf, bufY, E3);
    zero_stats<<<1, 256>>>(stats);
    inorm_partial<8, 8, 2048><<<dim3(E3 / 2048, 1, 2), 256>>>(bufY, E3, stats);
    inorm_apply_final<<<(2 * 8 * E3) / 256, 256>>>(bufY, E3, stats, outp);
}

// round 2
// speedup vs baseline: 1.0690x; 1.0690x over previous
#include <cuda_runtime.h>
#include <math.h>
#include <stdint.h>

// ---------------------------------------------------------------------------
// Static device scratch. Activations in (B, E, C) layout: x[(b*E+e)*C + c].
// ---------------------------------------------------------------------------
__device__ float  g_bufA[8388608];
__device__ float  g_bufB[8388608];
__device__ float  g_bufU[4194304];
__device__ float  g_bufY[8388608];
__device__ float  g_wt[400000];      // transposed weights [K=Cin*5][Cout]
__device__ double g_stats[1024];

// packed f32x2 helpers
#define FMA2(d, a, b) asm("fma.rn.f32x2 %0, %1, %2, %0;" : "+l"(d) : "l"(a), "l"(b))
#define PACK2(d, lo, hi) asm("mov.b64 %0, {%1, %2};" : "=l"(d) : "f"(lo), "f"(hi))
#define PACKB(d, v) asm("mov.b64 %0, {%1, %1};" : "=l"(d) : "f"(v))
#define UNPACK2(lo, hi, s) asm("mov.b64 {%0, %1}, %2;" : "=f"(lo), "=f"(hi) : "l"(s))

// ---------------------------------------------------------------------------
// Fused weight transpose: all 8 W (Cout, Cin, 5) -> Wt[k][o], k = c*5+s
// ---------------------------------------------------------------------------
__global__ void wtrans_all(const float* __restrict__ W0, const float* __restrict__ W1,
                           const float* __restrict__ W2, const float* __restrict__ W3,
                           const float* __restrict__ W4, const float* __restrict__ W5,
                           const float* __restrict__ W6, const float* __restrict__ W7,
                           float* __restrict__ wt)
{
    int i = blockIdx.x * 256 + threadIdx.x;
    if (i >= 324160) return;
    const int Ks[8]   = {1280, 640, 640, 320, 320, 160, 160, 40};
    const int Cs[8]   = {128, 128, 64, 64, 32, 32, 8, 8};
    const int offs[9] = {0, 163840, 245760, 286720, 307200, 317440, 322560, 323840, 324160};
    const float* Ws[8] = {W0, W1, W2, W3, W4, W5, W6, W7};
    int seg = 0;
    while (i >= offs[seg + 1]) seg++;
    int j = i - offs[seg];
    int K = Ks[seg], C = Cs[seg];
    int k = j / C, o = j % C;
    wt[i] = Ws[seg][(size_t)o * K + k];
}

__global__ void zero_stats_all(double* s) {
    int i = blockIdx.x * 256 + threadIdx.x;
    if (i < 1024) s[i] = 0.0;
}

// ---------------------------------------------------------------------------
// fe (B, C, E) -> (B, E, C) tiled transpose
// ---------------------------------------------------------------------------
__global__ void xpose(const float* __restrict__ in, float* __restrict__ outT,
                      int E, int C) {
    __shared__ float tile[32][33];
    int b = blockIdx.z;
    int e0 = blockIdx.x * 32, c0 = blockIdx.y * 32;
    int tx = threadIdx.x, ty = threadIdx.y;          // (32, 8)
    const float* inb = in + (size_t)b * C * E;
    float* ob = outT + (size_t)b * E * C;
#pragma unroll
    for (int j = 0; j < 32; j += 8)
        tile[ty + j][tx] = inb[(size_t)(c0 + ty + j) * E + e0 + tx];
    __syncthreads();
#pragma unroll
    for (int j = 0; j < 32; j += 8)
        ob[(size_t)(e0 + ty + j) * C + c0 + tx] = tile[tx][ty + j];
}

// ---------------------------------------------------------------------------
// Mesh-conv GEMM with packed f32x2 FMA and software-pipelined gathers.
// Block: 256 threads = GX(edge groups of 4) x GY(out groups of 8).
// Per thread: 4 edges x 8 outs accumulated in 16 f32x2 registers.
// ---------------------------------------------------------------------------
template<int CIN, int COUT, int BE, int CK>
__global__ __launch_bounds__(256) void conv_f2(
    const float* __restrict__ x, const int4* __restrict__ gemm,
    const float* __restrict__ Wt, const float* __restrict__ bias,
    float* __restrict__ out, int E)
{
    constexpr int TO = 8;
    constexpr int GX = BE / 4, GY = COUT / TO;
    static_assert(GX * GY == 256, "bad tile");
    constexpr int K5 = CK * 5;
    constexpr int ITEMS = BE * CK / 256;
    constexpr int CHUNKS = CIN / CK;
    constexpr int BEp = BE + 4;

    __shared__ __align__(16) float sG[K5][BEp];
    __shared__ __align__(16) float sW[K5][COUT];
    __shared__ int4 sIdx[BE];

    const int tid = threadIdx.x;
    const int b = blockIdx.y;
    const int e0 = blockIdx.x * BE;
    const float* xb = x + (size_t)b * E * CIN;

    for (int i = tid; i < BE; i += 256) sIdx[i] = gemm[e0 + i];
    __syncthreads();

    const int tx = tid % GX, ty = tid / GX;

    unsigned long long acc[4][4];
#pragma unroll
    for (int j = 0; j < 4; j++) {
        float b0 = bias[ty * TO + 2 * j], b1 = bias[ty * TO + 2 * j + 1];
        unsigned long long pb;
        PACK2(pb, b0, b1);
#pragma unroll
        for (int i = 0; i < 4; i++) acc[i][j] = pb;
    }

    float pf[ITEMS][5];
    // prologue gather: chunk 0
#pragma unroll
    for (int t = 0; t < ITEMS; t++) {
        int p = tid + t * 256;
        int cc = p % CK, el = p / CK;
        int c = cc;
        int4 n = sIdx[el];
        float xe = xb[(size_t)(e0 + el) * CIN + c];
        float f1 = xb[(size_t)n.x * CIN + c];
        float f2 = xb[(size_t)n.y * CIN + c];
        float f3 = xb[(size_t)n.z * CIN + c];
        float f4 = xb[(size_t)n.w * CIN + c];
        pf[t][0] = xe;
        pf[t][1] = f1 + f3; pf[t][2] = f2 + f4;
        pf[t][3] = fabsf(f1 - f3); pf[t][4] = fabsf(f2 - f4);
    }

    for (int chunk = 0; chunk < CHUNKS; chunk++) {
        __syncthreads();   // previous compute finished reading sG/sW
        // commit prefetched G tile
#pragma unroll
        for (int t = 0; t < ITEMS; t++) {
            int p = tid + t * 256;
            int cc = p % CK, el = p / CK;
            int kb = cc * 5;
#pragma unroll
            for (int s = 0; s < 5; s++) sG[kb + s][el] = pf[t][s];
        }
        // stage W chunk
        {
            const float4* wsrc = reinterpret_cast<const float4*>(Wt + (size_t)chunk * K5 * COUT);
            float4* wdst = reinterpret_cast<float4*>(&sW[0][0]);
            for (int i = tid; i < K5 * COUT / 4; i += 256) wdst[i] = wsrc[i];
        }
        __syncthreads();
        // prefetch next chunk's gathers (latency overlapped with compute below)
        if (chunk + 1 < CHUNKS) {
            int c0n = (chunk + 1) * CK;
#pragma unroll
            for (int t = 0; t < ITEMS; t++) {
                int p = tid + t * 256;
                int cc = p % CK, el = p / CK;
                int c = c0n + cc;
                int4 n = sIdx[el];
                float xe = xb[(size_t)(e0 + el) * CIN + c];
                float f1 = xb[(size_t)n.x * CIN + c];
                float f2 = xb[(size_t)n.y * CIN + c];
                float f3 = xb[(size_t)n.z * CIN + c];
                float f4 = xb[(size_t)n.w * CIN + c];
                pf[t][0] = xe;
                pf[t][1] = f1 + f3; pf[t][2] = f2 + f4;
                pf[t][3] = fabsf(f1 - f3); pf[t][4] = fabsf(f2 - f4);
            }
        }
        // compute: f32x2 packed FMA
#pragma unroll 5
        for (int k = 0; k < K5; k++) {
            float4 a4 = *reinterpret_cast<const float4*>(&sG[k][tx * 4]);
            unsigned long long pa0, pa1, pa2, pa3;
            PACKB(pa0, a4.x); PACKB(pa1, a4.y); PACKB(pa2, a4.z); PACKB(pa3, a4.w);
            const ulonglong2* wp = reinterpret_cast<const ulonglong2*>(&sW[k][ty * TO]);
            ulonglong2 wA = wp[0];
            ulonglong2 wB = wp[1];
            FMA2(acc[0][0], pa0, wA.x); FMA2(acc[0][1], pa0, wA.y);
            FMA2(acc[0][2], pa0, wB.x); FMA2(acc[0][3], pa0, wB.y);
            FMA2(acc[1][0], pa1, wA.x); FMA2(acc[1][1], pa1, wA.y);
            FMA2(acc[1][2], pa1, wB.x); FMA2(acc[1][3], pa1, wB.y);
            FMA2(acc[2][0], pa2, wA.x); FMA2(acc[2][1], pa2, wA.y);
            FMA2(acc[2][2], pa2, wB.x); FMA2(acc[2][3], pa2, wB.y);
            FMA2(acc[3][0], pa3, wA.x); FMA2(acc[3][1], pa3, wA.y);
            FMA2(acc[3][2], pa3, wB.x); FMA2(acc[3][3], pa3, wB.y);
        }
    }
    // epilogue
#pragma unroll
    for (int i = 0; i < 4; i++) {
        float ov[8];
#pragma unroll
        for (int j = 0; j < 4; j++) UNPACK2(ov[2 * j], ov[2 * j + 1], acc[i][j]);
        float* po = out + ((size_t)b * E + (e0 + tx * 4 + i)) * COUT + ty * TO;
        *reinterpret_cast<float4*>(po)     = make_float4(ov[0], ov[1], ov[2], ov[3]);
        *reinterpret_cast<float4*>(po + 4) = make_float4(ov[4], ov[5], ov[6], ov[7]);
    }
}

// ---------------------------------------------------------------------------
// Small-Cout mesh-conv (COUT = 8): one thread per edge, vectorized row loads.
// ---------------------------------------------------------------------------
template<int CIN>
__global__ __launch_bounds__(256) void conv_small(
    const float* __restrict__ x, const int4* __restrict__ gemm,
    const float* __restrict__ Wt, const float* __restrict__ bias,
    float* __restrict__ out, int E)
{
    constexpr int K = CIN * 5;
    __shared__ float sW[K * 8];
    int tid = threadIdx.x;
    for (int i = tid; i < K * 8; i += 256) sW[i] = Wt[i];
    float acc[8];
#pragma unroll
    for (int o = 0; o < 8; o++) acc[o] = bias[o];
    __syncthreads();

    int b = blockIdx.y;
    int e = blockIdx.x * 256 + tid;
    int4 n = gemm[e];
    const float* xb = x + (size_t)b * E * CIN;
    const float4* r0 = reinterpret_cast<const float4*>(xb + (size_t)e * CIN);
    const float4* r1 = reinterpret_cast<const float4*>(xb + (size_t)n.x * CIN);
    const float4* r2 = reinterpret_cast<const float4*>(xb + (size_t)n.y * CIN);
    const float4* r3 = reinterpret_cast<const float4*>(xb + (size_t)n.z * CIN);
    const float4* r4 = reinterpret_cast<const float4*>(xb + (size_t)n.w * CIN);

#pragma unroll 2
    for (int c4 = 0; c4 < CIN / 4; c4++) {
        float4 xe = r0[c4], a1 = r1[c4], a2 = r2[c4], a3 = r3[c4], a4 = r4[c4];
#define PROC(COMP, CC)                                                         \
        {                                                                      \
            float g0 = xe.COMP;                                                \
            float s1 = a1.COMP + a3.COMP;                                      \
            float s2 = a2.COMP + a4.COMP;                                      \
            float d1 = fabsf(a1.COMP - a3.COMP);                               \
            float d2 = fabsf(a2.COMP - a4.COMP);                               \
            const float* w = &sW[(c4 * 4 + CC) * 5 * 8];                       \
            for (int o = 0; o < 8; o++)                                        \
                acc[o] += g0 * w[o] + s1 * w[8 + o] + s2 * w[16 + o]           \
                        + d1 * w[24 + o] + d2 * w[32 + o];                     \
        }
        PROC(x, 0) PROC(y, 1) PROC(z, 2) PROC(w, 3)
#undef PROC
    }
    float* po = out + ((size_t)b * E + e) * 8;
    *reinterpret_cast<float4*>(po)     = make_float4(acc[0], acc[1], acc[2], acc[3]);
    *reinterpret_cast<float4*>(po + 4) = make_float4(acc[4], acc[5], acc[6], acc[7]);
}

// ---------------------------------------------------------------------------
// unpool + skip: out[b,e,c] = up[b, unpool[e], c] + skip[b,c,e]
// ---------------------------------------------------------------------------
template<int C>
__global__ __launch_bounds__(256) void unpool_skip(
    const float* __restrict__ up, const int* __restrict__ unpool,
    const float* __restrict__ skip, float* __restrict__ out,
    int Eout, int Ein)
{
    constexpr int TE = 32;
    __shared__ float ssk[C][TE + 1];
    __shared__ int su[TE];
    int tid = threadIdx.x;
    int b = blockIdx.y;
    int e0 = blockIdx.x * TE;
    if (tid < TE) su[tid] = unpool[e0 + tid];
    const float* skb = skip + (size_t)b * C * Eout;
    for (int i = tid; i < C * TE; i += 256) {
        int c = i >> 5, e = i & 31;
        ssk[c][e] = skb[(size_t)c * Eout + e0 + e];
    }
    __syncthreads();
    const float* upb = up + (size_t)b * Ein * C;
    float* ob = out + ((size_t)b * Eout + e0) * C;
    for (int i = tid; i < C * TE; i += 256) {
        int el = i / C, c = i % C;
        ob[(size_t)el * C + c] = upb[(size_t)su[el] * C + c] + ssk[c][el];
    }
}

// ---------------------------------------------------------------------------
// Instance norm: split partial reduction, then normalize + relu.
// ---------------------------------------------------------------------------
template<int C, int CG, int CHUNK>
__global__ __launch_bounds__(256) void inorm_partial(
    const float* __restrict__ x, int E, double* __restrict__ stats)
{
    constexpr int LANES = 256 / CG;
    __shared__ float rs[256], rs2[256];
    int tid = threadIdx.x;
    int cl = tid % CG, lane = tid / CG;
    int b = blockIdx.z;
    int c = blockIdx.y * CG + cl;
    int e0 = blockIdx.x * CHUNK;
    const float* xb = x + (size_t)b * E * C;
    float s = 0.f, s2 = 0.f;
    for (int e = e0 + lane; e < e0 + CHUNK; e += LANES) {
        float v = xb[(size_t)e * C + c];
        s += v; s2 += v * v;
    }
    rs[tid] = s; rs2[tid] = s2;
    __syncthreads();
    for (int st = 128; st >= CG; st >>= 1) {
        if (tid < st) { rs[tid] += rs[tid + st]; rs2[tid] += rs2[tid + st]; }
        __syncthreads();
    }
    if (tid < CG) {
        int cc = blockIdx.y * CG + tid;
        atomicAdd(&stats[(b * C + cc) * 2],     (double)rs[tid]);
        atomicAdd(&stats[(b * C + cc) * 2 + 1], (double)rs2[tid]);
    }
}

template<int C>
__global__ __launch_bounds__(256) void inorm_apply(
    float* __restrict__ x, int E, const double* __restrict__ stats)
{
    int idx = blockIdx.x * 256 + threadIdx.x;
    int c = idx % C;
    int be = idx / C;
    int b = be / E;
    double s  = stats[(b * C + c) * 2];
    double s2 = stats[(b * C + c) * 2 + 1];
    double m = s / E;
    double var = s2 / E - m * m;
    float r = rsqrtf((float)var + 1e-5f);
    float v = (x[idx] - (float)m) * r;
    x[idx] = v > 0.f ? v : 0.f;
}

__global__ __launch_bounds__(256) void inorm_apply_final(
    const float* __restrict__ x, int E, const double* __restrict__ stats,
    float* __restrict__ out)
{
    int idx = blockIdx.x * 256 + threadIdx.x;   // output layout (b*8+c)*E + e
    int e = idx % E;
    int t = idx / E;
    int c = t % 8;
    int b = t / 8;
    double s  = stats[(b * 8 + c) * 2];
    double s2 = stats[(b * 8 + c) * 2 + 1];
    double m = s / E;
    double var = s2 / E - m * m;
    float r = rsqrtf((float)var + 1e-5f);
    float v = (x[((size_t)b * E + e) * 8 + c] - (float)m) * r;
    out[idx] = v > 0.f ? v : 0.f;
}

// ---------------------------------------------------------------------------
// Host driver
// ---------------------------------------------------------------------------
extern "C" void kernel_launch(void* const* d_in, const int* in_sizes, int n_in,
                              void* d_out, int out_size)
{
    (void)in_sizes; (void)n_in; (void)out_size;
    const int E0 = 16384, E1 = 32768, E2 = 65536, E3 = 131072;

    const float* fe    = (const float*)d_in[0];
    const float* skip0 = (const float*)d_in[1];
    const float* skip1 = (const float*)d_in[2];
    const float* skip2 = (const float*)d_in[3];
    const int4*  gm0   = (const int4*)d_in[4];
    const int4*  gm1   = (const int4*)d_in[5];
    const int4*  gm2   = (const int4*)d_in[6];
    const int4*  gm3   = (const int4*)d_in[7];
    const int*   up0   = (const int*)d_in[8];
    const int*   up1   = (const int*)d_in[9];
    const int*   up2   = (const int*)d_in[10];
    const float* Wup0 = (const float*)d_in[11]; const float* bup0 = (const float*)d_in[12];
    const float* Wc0  = (const float*)d_in[13]; const float* bc0  = (const float*)d_in[14];
    const float* Wup1 = (const float*)d_in[15]; const float* bup1 = (const float*)d_in[16];
    const float* Wc1  = (const float*)d_in[17]; const float* bc1  = (const float*)d_in[18];
    const float* Wup2 = (const float*)d_in[19]; const float* bup2 = (const float*)d_in[20];
    const float* Wc2  = (const float*)d_in[21]; const float* bc2  = (const float*)d_in[22];
    const float* Wupf = (const float*)d_in[23]; const float* bupf = (const float*)d_in[24];
    const float* Wcf  = (const float*)d_in[25]; const float* bcf  = (const float*)d_in[26];
    float* outp = (float*)d_out;

    float *bufA, *bufB, *bufU, *bufY, *wt; double* stats;
    cudaGetSymbolAddress((void**)&bufA, g_bufA);
    cudaGetSymbolAddress((void**)&bufB, g_bufB);
    cudaGetSymbolAddress((void**)&bufU, g_bufU);
    cudaGetSymbolAddress((void**)&bufY, g_bufY);
    cudaGetSymbolAddress((void**)&wt,   g_wt);
    cudaGetSymbolAddress((void**)&stats, g_stats);

    float* Wt_up0 = wt;
    float* Wt_c0  = wt + 163840;
    float* Wt_up1 = wt + 245760;
    float* Wt_c1  = wt + 286720;
    float* Wt_up2 = wt + 307200;
    float* Wt_c2  = wt + 317440;
    float* Wt_upf = wt + 322560;
    float* Wt_cf  = wt + 323840;

    double* stats0 = stats;          // 2*128*2 = 512
    double* stats1 = stats + 512;    // 2*64*2  = 256
    double* stats2 = stats + 768;    // 2*32*2  = 128
    double* statsF = stats + 896;    // 2*8*2   = 32

    // #0: fused weight transpose    #1: zero stats    #2: fe transpose
    wtrans_all<<<1267, 256>>>(Wup0, Wc0, Wup1, Wc1, Wup2, Wc2, Wupf, Wcf, wt);
    zero_stats_all<<<4, 256>>>(stats);
    xpose<<<dim3(E0 / 32, 256 / 32, 2), dim3(32, 8)>>>(fe, bufA, E0, 256);

    // ---- Level 0 ----  (#3 up0, #4 unpool, #5 c0 <- ncu capture target)
    conv_f2<256, 128, 64, 8><<<dim3(E0 / 64, 2), 256>>>(bufA, gm0, Wt_up0, bup0, bufU, E0);
    unpool_skip<128><<<dim3(E1 / 32, 2), 256>>>(bufU, up0, skip0, bufY, E1, E0);
    conv_f2<128, 128, 64, 8><<<dim3(E1 / 64, 2), 256>>>(bufY, gm1, Wt_c0, bc0, bufB, E1);
    inorm_partial<128, 32, 2048><<<dim3(E1 / 2048, 4, 2), 256>>>(bufB, E1, stats0);
    inorm_apply<128><<<(2 * E1 * 128) / 256, 256>>>(bufB, E1, stats0);

    // ---- Level 1 ----
    conv_f2<128, 64, 128, 8><<<dim3(E1 / 128, 2), 256>>>(bufB, gm1, Wt_up1, bup1, bufU, E1);
    unpool_skip<64><<<dim3(E2 / 32, 2), 256>>>(bufU, up1, skip1, bufY, E2, E1);
    conv_f2<64, 64, 128, 8><<<dim3(E2 / 128, 2), 256>>>(bufY, gm2, Wt_c1, bc1, bufA, E2);
    inorm_partial<64, 32, 2048><<<dim3(E2 / 2048, 2, 2), 256>>>(bufA, E2, stats1);
    inorm_apply<64><<<(2 * E2 * 64) / 256, 256>>>(bufA, E2, stats1);

    // ---- Level 2 ----
    conv_f2<64, 32, 256, 4><<<dim3(E2 / 256, 2), 256>>>(bufA, gm2, Wt_up2, bup2, bufU, E2);
    unpool_skip<32><<<dim3(E3 / 32, 2), 256>>>(bufU, up2, skip2, bufY, E3, E2);
    conv_f2<32, 32, 256, 4><<<dim3(E3 / 256, 2), 256>>>(bufY, gm3, Wt_c2, bc2, bufB, E3);
    inorm_partial<32, 32, 2048><<<dim3(E3 / 2048, 1, 2), 256>>>(bufB, E3, stats2);
    inorm_apply<32><<<(2 * E3 * 32) / 256, 256>>>(bufB, E3, stats2);

    // ---- Final ----
    conv_small<32><<<dim3(E3 / 256, 2), 256>>>(bufB, gm3, Wt_upf, bupf, bufU, E3);
    conv_small<8><<<dim3(E3 / 256, 2), 256>>>(bufU, gm3, Wt_cf, bcf, bufY, E3);
    inorm_partial<8, 8, 2048><<<dim3(E3 / 2048, 1, 2), 256>>>(bufY, E3, statsF);
    inorm_apply_final<<<(2 * 8 * E3) / 256, 256>>>(bufY, E3, statsF, outp);
}

// round 3
// speedup vs baseline: 1.6329x; 1.5276x over previous
#include <cuda_runtime.h>
#include <math.h>
#include <stdint.h>

// ---------------------------------------------------------------------------
// Static device scratch. Activations in (B, E, C) layout: x[(b*E+e)*C + c].
// ---------------------------------------------------------------------------
__device__ float  g_bufA[8388608];
__device__ float  g_bufB[8388608];
__device__ float  g_bufU[4194304];
__device__ float  g_bufY[8388608];
__device__ float  g_wt[400000];      // transposed weights [K=Cin*5][Cout]
__device__ double g_stats[1024];
__device__ float2 g_mstat[512];      // (mean, rsqrt(var+eps)) per (b,c)

// packed f32x2 helpers
#define FMA2(d, a, b) asm("fma.rn.f32x2 %0, %1, %2, %0;" : "+l"(d) : "l"(a), "l"(b))
#define PACK2(d, lo, hi) asm("mov.b64 %0, {%1, %2};" : "=l"(d) : "f"(lo), "f"(hi))
#define PACKB(d, v) asm("mov.b64 %0, {%1, %1};" : "=l"(d) : "f"(v))
#define UNPACK2(lo, hi, s) asm("mov.b64 {%0, %1}, %2;" : "=f"(lo), "=f"(hi) : "l"(s))

// ---------------------------------------------------------------------------
// Fused weight transpose: all 8 W (Cout, Cin, 5) -> Wt[k][o], k = c*5+s
// ---------------------------------------------------------------------------
__global__ void wtrans_all(const float* __restrict__ W0, const float* __restrict__ W1,
                           const float* __restrict__ W2, const float* __restrict__ W3,
                           const float* __restrict__ W4, const float* __restrict__ W5,
                           const float* __restrict__ W6, const float* __restrict__ W7,
                           float* __restrict__ wt)
{
    int i = blockIdx.x * 256 + threadIdx.x;
    if (i >= 324160) return;
    const int Ks[8]   = {1280, 640, 640, 320, 320, 160, 160, 40};
    const int Cs[8]   = {128, 128, 64, 64, 32, 32, 8, 8};
    const int offs[9] = {0, 163840, 245760, 286720, 307200, 317440, 322560, 323840, 324160};
    const float* Ws[8] = {W0, W1, W2, W3, W4, W5, W6, W7};
    int seg = 0;
    while (i >= offs[seg + 1]) seg++;
    int j = i - offs[seg];
    int K = Ks[seg], C = Cs[seg];
    int k = j / C, o = j % C;
    wt[i] = Ws[seg][(size_t)o * K + k];
}

__global__ void zero_stats_all(double* s) {
    int i = blockIdx.x * 256 + threadIdx.x;
    if (i < 1024) s[i] = 0.0;
}

// ---------------------------------------------------------------------------
// fe (B, C, E) -> (B, E, C) tiled transpose
// ---------------------------------------------------------------------------
__global__ void xpose(const float* __restrict__ in, float* __restrict__ outT,
                      int E, int C) {
    __shared__ float tile[32][33];
    int b = blockIdx.z;
    int e0 = blockIdx.x * 32, c0 = blockIdx.y * 32;
    int tx = threadIdx.x, ty = threadIdx.y;          // (32, 8)
    const float* inb = in + (size_t)b * C * E;
    float* ob = outT + (size_t)b * E * C;
#pragma unroll
    for (int j = 0; j < 32; j += 8)
        tile[ty + j][tx] = inb[(size_t)(c0 + ty + j) * E + e0 + tx];
    __syncthreads();
#pragma unroll
    for (int j = 0; j < 32; j += 8)
        ob[(size_t)(e0 + ty + j) * C + c0 + tx] = tile[tx][ty + j];
}

// ---------------------------------------------------------------------------
// Mesh-conv GEMM, packed f32x2 FMA, software-pipelined gathers.
// 256 threads = GX(edge groups of 4) x GY(out groups of 8); 4 edges x 8 outs.
// DUP (COUT<=64): edges packed in pairs, W duplicated in smem -> no movs.
// else: W packed in out-pairs, edges broadcast via PACKB.
// ---------------------------------------------------------------------------
template<int CIN, int COUT, int BE, int CK>
__global__ __launch_bounds__(256) void conv_f2(
    const float* __restrict__ x, const int4* __restrict__ gemm,
    const float* __restrict__ Wt, const float* __restrict__ bias,
    float* __restrict__ out, int E)
{
    constexpr int TO = 8;
    constexpr int GX = BE / 4, GY = COUT / TO;
    static_assert(GX * GY == 256, "bad tile");
    constexpr int K5 = CK * 5;
    constexpr int ITEMS = BE * CK / 256;
    constexpr int CHUNKS = CIN / CK;
    constexpr int BEp = BE + 4;
    constexpr bool DUP = (COUT <= 64);
    constexpr int WROW = DUP ? 2 * COUT : COUT;

    __shared__ __align__(16) float sG[K5][BEp];
    __shared__ __align__(16) float sW[K5][WROW];
    __shared__ int4 sIdx[BE];

    const int tid = threadIdx.x;
    const int b = blockIdx.y;
    const int e0 = blockIdx.x * BE;
    const float* xb = x + (size_t)b * E * CIN;

    for (int i = tid; i < BE; i += 256) sIdx[i] = gemm[e0 + i];
    __syncthreads();

    const int tx = tid % GX, ty = tid / GX;

    unsigned long long acc[16];
    if constexpr (DUP) {
#pragma unroll
        for (int j = 0; j < 8; j++) {
            unsigned long long pb;
            PACKB(pb, bias[ty * TO + j]);
            acc[j] = pb; acc[8 + j] = pb;
        }
    } else {
#pragma unroll
        for (int j = 0; j < 4; j++) {
            unsigned long long pb;
            PACK2(pb, bias[ty * TO + 2 * j], bias[ty * TO + 2 * j + 1]);
#pragma unroll
            for (int i = 0; i < 4; i++) acc[i * 4 + j] = pb;
        }
    }

    float pf[ITEMS][5];
#pragma unroll
    for (int t = 0; t < ITEMS; t++) {
        int p = tid + t * 256;
        int cc = p % CK, el = p / CK;
        int4 n = sIdx[el];
        float xe = xb[(size_t)(e0 + el) * CIN + cc];
        float f1 = xb[(size_t)n.x * CIN + cc];
        float f2 = xb[(size_t)n.y * CIN + cc];
        float f3 = xb[(size_t)n.z * CIN + cc];
        float f4 = xb[(size_t)n.w * CIN + cc];
        pf[t][0] = xe;
        pf[t][1] = f1 + f3; pf[t][2] = f2 + f4;
        pf[t][3] = fabsf(f1 - f3); pf[t][4] = fabsf(f2 - f4);
    }

    for (int chunk = 0; chunk < CHUNKS; chunk++) {
        __syncthreads();
#pragma unroll
        for (int t = 0; t < ITEMS; t++) {
            int p = tid + t * 256;
            int cc = p % CK, el = p / CK;
            int kb = cc * 5;
#pragma unroll
            for (int s = 0; s < 5; s++) sG[kb + s][el] = pf[t][s];
        }
        // stage W chunk
        {
            const float4* wsrc = reinterpret_cast<const float4*>(Wt + (size_t)chunk * K5 * COUT);
            if constexpr (DUP) {
                for (int i = tid; i < K5 * COUT / 4; i += 256) {
                    float4 w = wsrc[i];
                    int f = i * 4;
                    int k = f / COUT, o = f % COUT;
                    *reinterpret_cast<float4*>(&sW[k][2 * o])     = make_float4(w.x, w.x, w.y, w.y);
                    *reinterpret_cast<float4*>(&sW[k][2 * o + 4]) = make_float4(w.z, w.z, w.w, w.w);
                }
            } else {
                float4* wdst = reinterpret_cast<float4*>(&sW[0][0]);
                for (int i = tid; i < K5 * COUT / 4; i += 256) wdst[i] = wsrc[i];
            }
        }
        __syncthreads();
        if (chunk + 1 < CHUNKS) {
            int c0n = (chunk + 1) * CK;
#pragma unroll
            for (int t = 0; t < ITEMS; t++) {
                int p = tid + t * 256;
                int cc = p % CK, el = p / CK;
                int c = c0n + cc;
                int4 n = sIdx[el];
                float xe = xb[(size_t)(e0 + el) * CIN + c];
                float f1 = xb[(size_t)n.x * CIN + c];
                float f2 = xb[(size_t)n.y * CIN + c];
                float f3 = xb[(size_t)n.z * CIN + c];
                float f4 = xb[(size_t)n.w * CIN + c];
                pf[t][0] = xe;
                pf[t][1] = f1 + f3; pf[t][2] = f2 + f4;
                pf[t][3] = fabsf(f1 - f3); pf[t][4] = fabsf(f2 - f4);
            }
        }
#pragma unroll 5
        for (int k = 0; k < K5; k++) {
            if constexpr (DUP) {
                ulonglong2 aP = *reinterpret_cast<const ulonglong2*>(&sG[k][tx * 4]);
                const ulonglong2* wp = reinterpret_cast<const ulonglong2*>(&sW[k][ty * 16]);
                ulonglong2 w0 = wp[0], w1 = wp[1], w2 = wp[2], w3 = wp[3];
                FMA2(acc[0], aP.x, w0.x); FMA2(acc[1], aP.x, w0.y);
                FMA2(acc[2], aP.x, w1.x); FMA2(acc[3], aP.x, w1.y);
                FMA2(acc[4], aP.x, w2.x); FMA2(acc[5], aP.x, w2.y);
                FMA2(acc[6], aP.x, w3.x); FMA2(acc[7], aP.x, w3.y);
                FMA2(acc[8],  aP.y, w0.x); FMA2(acc[9],  aP.y, w0.y);
                FMA2(acc[10], aP.y, w1.x); FMA2(acc[11], aP.y, w1.y);
                FMA2(acc[12], aP.y, w2.x); FMA2(acc[13], aP.y, w2.y);
                FMA2(acc[14], aP.y, w3.x); FMA2(acc[15], aP.y, w3.y);
            } else {
                float4 a4 = *reinterpret_cast<const float4*>(&sG[k][tx * 4]);
                unsigned long long pa0, pa1, pa2, pa3;
                PACKB(pa0, a4.x); PACKB(pa1, a4.y); PACKB(pa2, a4.z); PACKB(pa3, a4.w);
                const ulonglong2* wp = reinterpret_cast<const ulonglong2*>(&sW[k][ty * TO]);
                ulonglong2 wA = wp[0];
                ulonglong2 wB = wp[1];
                FMA2(acc[0],  pa0, wA.x); FMA2(acc[1],  pa0, wA.y);
                FMA2(acc[2],  pa0, wB.x); FMA2(acc[3],  pa0, wB.y);
                FMA2(acc[4],  pa1, wA.x); FMA2(acc[5],  pa1, wA.y);
                FMA2(acc[6],  pa1, wB.x); FMA2(acc[7],  pa1, wB.y);
                FMA2(acc[8],  pa2, wA.x); FMA2(acc[9],  pa2, wA.y);
                FMA2(acc[10], pa2, wB.x); FMA2(acc[11], pa2, wB.y);
                FMA2(acc[12], pa3, wA.x); FMA2(acc[13], pa3, wA.y);
                FMA2(acc[14], pa3, wB.x); FMA2(acc[15], pa3, wB.y);
            }
        }
    }
    // epilogue
    if constexpr (DUP) {
#pragma unroll
        for (int p = 0; p < 2; p++) {
            float lo[8], hi[8];
#pragma unroll
            for (int j = 0; j < 8; j++) UNPACK2(lo[j], hi[j], acc[p * 8 + j]);
            float* p0 = out + ((size_t)b * E + (e0 + tx * 4 + 2 * p)) * COUT + ty * TO;
            float* p1 = p0 + COUT;
            *reinterpret_cast<float4*>(p0)     = make_float4(lo[0], lo[1], lo[2], lo[3]);
            *reinterpret_cast<float4*>(p0 + 4) = make_float4(lo[4], lo[5], lo[6], lo[7]);
            *reinterpret_cast<float4*>(p1)     = make_float4(hi[0], hi[1], hi[2], hi[3]);
            *reinterpret_cast<float4*>(p1 + 4) = make_float4(hi[4], hi[5], hi[6], hi[7]);
        }
    } else {
#pragma unroll
        for (int i = 0; i < 4; i++) {
            float ov[8];
#pragma unroll
            for (int j = 0; j < 4; j++) UNPACK2(ov[2 * j], ov[2 * j + 1], acc[i * 4 + j]);
            float* po = out + ((size_t)b * E + (e0 + tx * 4 + i)) * COUT + ty * TO;
            *reinterpret_cast<float4*>(po)     = make_float4(ov[0], ov[1], ov[2], ov[3]);
            *reinterpret_cast<float4*>(po + 4) = make_float4(ov[4], ov[5], ov[6], ov[7]);
        }
    }
}

// ---------------------------------------------------------------------------
// Small-Cout mesh-conv (COUT = 8)
// ---------------------------------------------------------------------------
template<int CIN>
__global__ __launch_bounds__(256) void conv_small(
    const float* __restrict__ x, const int4* __restrict__ gemm,
    const float* __restrict__ Wt, const float* __restrict__ bias,
    float* __restrict__ out, int E)
{
    constexpr int K = CIN * 5;
    __shared__ float sW[K * 8];
    int tid = threadIdx.x;
    for (int i = tid; i < K * 8; i += 256) sW[i] = Wt[i];
    float acc[8];
#pragma unroll
    for (int o = 0; o < 8; o++) acc[o] = bias[o];
    __syncthreads();

    int b = blockIdx.y;
    int e = blockIdx.x * 256 + tid;
    int4 n = gemm[e];
    const float* xb = x + (size_t)b * E * CIN;
    const float4* r0 = reinterpret_cast<const float4*>(xb + (size_t)e * CIN);
    const float4* r1 = reinterpret_cast<const float4*>(xb + (size_t)n.x * CIN);
    const float4* r2 = reinterpret_cast<const float4*>(xb + (size_t)n.y * CIN);
    const float4* r3 = reinterpret_cast<const float4*>(xb + (size_t)n.z * CIN);
    const float4* r4 = reinterpret_cast<const float4*>(xb + (size_t)n.w * CIN);

#pragma unroll 2
    for (int c4 = 0; c4 < CIN / 4; c4++) {
        float4 xe = r0[c4], a1 = r1[c4], a2 = r2[c4], a3 = r3[c4], a4 = r4[c4];
#define PROC(COMP, CC)                                                         \
        {                                                                      \
            float g0 = xe.COMP;                                                \
            float s1 = a1.COMP + a3.COMP;                                      \
            float s2 = a2.COMP + a4.COMP;                                      \
            float d1 = fabsf(a1.COMP - a3.COMP);                               \
            float d2 = fabsf(a2.COMP - a4.COMP);                               \
            const float* w = &sW[(c4 * 4 + CC) * 5 * 8];                       \
            for (int o = 0; o < 8; o++)                                        \
                acc[o] += g0 * w[o] + s1 * w[8 + o] + s2 * w[16 + o]           \
                        + d1 * w[24 + o] + d2 * w[32 + o];                     \
        }
        PROC(x, 0) PROC(y, 1) PROC(z, 2) PROC(w, 3)
#undef PROC
    }
    float* po = out + ((size_t)b * E + e) * 8;
    *reinterpret_cast<float4*>(po)     = make_float4(acc[0], acc[1], acc[2], acc[3]);
    *reinterpret_cast<float4*>(po + 4) = make_float4(acc[4], acc[5], acc[6], acc[7]);
}

// ---------------------------------------------------------------------------
// unpool + skip
// ---------------------------------------------------------------------------
template<int C>
__global__ __launch_bounds__(256) void unpool_skip(
    const float* __restrict__ up, const int* __restrict__ unpool,
    const float* __restrict__ skip, float* __restrict__ out,
    int Eout, int Ein)
{
    constexpr int TE = 32;
    __shared__ float ssk[C][TE + 1];
    __shared__ int su[TE];
    int tid = threadIdx.x;
    int b = blockIdx.y;
    int e0 = blockIdx.x * TE;
    if (tid < TE) su[tid] = unpool[e0 + tid];
    const float* skb = skip + (size_t)b * C * Eout;
    for (int i = tid; i < C * TE; i += 256) {
        int c = i >> 5, e = i & 31;
        ssk[c][e] = skb[(size_t)c * Eout + e0 + e];
    }
    __syncthreads();
    const float* upb = up + (size_t)b * Ein * C;
    float* ob = out + ((size_t)b * Eout + e0) * C;
    for (int i = tid; i < C * TE; i += 256) {
        int el = i / C, c = i % C;
        ob[(size_t)el * C + c] = upb[(size_t)su[el] * C + c] + ssk[c][el];
    }
}

// ---------------------------------------------------------------------------
// Instance norm, coalesced partial reduction: lane -> channel-float4.
// ---------------------------------------------------------------------------
template<int C, int CHUNK>
__global__ __launch_bounds__(256) void inorm_partial(
    const float* __restrict__ x, int E, double* __restrict__ stats)
{
    constexpr int C4 = C / 4;
    constexpr int ESTEP = 256 / C4;
    __shared__ float rb[256][8];
    int tid = threadIdx.x;
    int c4 = tid % C4, er = tid / C4;
    int b = blockIdx.z;
    int e0 = blockIdx.x * CHUNK;
    const float4* xb4 = reinterpret_cast<const float4*>(x + ((size_t)b * E + e0) * C) + c4;
    float s0 = 0, s1 = 0, s2 = 0, s3 = 0, q0 = 0, q1 = 0, q2 = 0, q3 = 0;
    for (int e = er; e < CHUNK; e += ESTEP) {
        float4 v = xb4[(size_t)e * C4];
        s0 += v.x; q0 += v.x * v.x;
        s1 += v.y; q1 += v.y * v.y;
        s2 += v.z; q2 += v.z * v.z;
        s3 += v.w; q3 += v.w * v.w;
    }
    rb[tid][0] = s0; rb[tid][1] = s1; rb[tid][2] = s2; rb[tid][3] = s3;
    rb[tid][4] = q0; rb[tid][5] = q1; rb[tid][6] = q2; rb[tid][7] = q3;
    __syncthreads();
    for (int st = ESTEP / 2; st >= 1; st >>= 1) {
        if (er < st) {
#pragma unroll
            for (int u = 0; u < 8; u++) rb[tid][u] += rb[tid + st * C4][u];
        }
        __syncthreads();
    }
    if (er == 0) {
#pragma unroll
        for (int u = 0; u < 4; u++) {
            atomicAdd(&stats[((size_t)b * C + c4 * 4 + u) * 2],     (double)rb[tid][u]);
            atomicAdd(&stats[((size_t)b * C + c4 * 4 + u) * 2 + 1], (double)rb[tid][4 + u]);
        }
    }
}

// stats -> (mean, rinv) float2, one thread per (b,c)
__global__ void finalize_stats(const double* __restrict__ stats,
                               float2* __restrict__ mstat, int n, int E)
{
    int i = threadIdx.x;
    if (i >= n) return;
    double invE = 1.0 / (double)E;
    double m = stats[2 * i] * invE;
    double var = stats[2 * i + 1] * invE - m * m;
    mstat[i] = make_float2((float)m, rsqrtf((float)var + 1e-5f));
}

template<int C>
__global__ __launch_bounds__(256) void inorm_apply(
    float* __restrict__ x, int E, const float2* __restrict__ mstat)
{
    int idx = blockIdx.x * 256 + threadIdx.x;
    int c = idx % C;
    int b = idx / (E * C);
    float2 mr = mstat[b * C + c];
    float v = (x[idx] - mr.x) * mr.y;
    x[idx] = v > 0.f ? v : 0.f;
}

// Final: reads (B,E,8), writes d_out (B,8,E) with norm+relu, smem transpose.
__global__ __launch_bounds__(256) void inorm_apply_final(
    const float* __restrict__ x, int E, const float2* __restrict__ mstat,
    float* __restrict__ out)
{
    __shared__ float sm[256];
    int tid = threadIdx.x;
    int b = blockIdx.y;
    int e0 = blockIdx.x * 32;
    float2 mr = mstat[b * 8 + (tid & 7)];
    float v = (x[((size_t)b * E + e0) * 8 + tid] - mr.x) * mr.y;
    sm[tid] = v > 0.f ? v : 0.f;
    __syncthreads();
    int c = tid >> 5, el = tid & 31;
    out[((size_t)b * 8 + c) * E + e0 + el] = sm[el * 8 + c];
}

// ---------------------------------------------------------------------------
// Host driver
// ---------------------------------------------------------------------------
extern "C" void kernel_launch(void* const* d_in, const int* in_sizes, int n_in,
                              void* d_out, int out_size)
{
    (void)in_sizes; (void)n_in; (void)out_size;
    const int E0 = 16384, E1 = 32768, E2 = 65536, E3 = 131072;

    const float* fe    = (const float*)d_in[0];
    const float* skip0 = (const float*)d_in[1];
    const float* skip1 = (const float*)d_in[2];
    const float* skip2 = (const float*)d_in[3];
    const int4*  gm0   = (const int4*)d_in[4];
    const int4*  gm1   = (const int4*)d_in[5];
    const int4*  gm2   = (const int4*)d_in[6];
    const int4*  gm3   = (const int4*)d_in[7];
    const int*   up0   = (const int*)d_in[8];
    const int*   up1   = (const int*)d_in[9];
    const int*   up2   = (const int*)d_in[10];
    const float* Wup0 = (const float*)d_in[11]; const float* bup0 = (const float*)d_in[12];
    const float* Wc0  = (const float*)d_in[13]; const float* bc0  = (const float*)d_in[14];
    const float* Wup1 = (const float*)d_in[15]; const float* bup1 = (const float*)d_in[16];
    const float* Wc1  = (const float*)d_in[17]; const float* bc1  = (const float*)d_in[18];
    const float* Wup2 = (const float*)d_in[19]; const float* bup2 = (const float*)d_in[20];
    const float* Wc2  = (const float*)d_in[21]; const float* bc2  = (const float*)d_in[22];
    const float* Wupf = (const float*)d_in[23]; const float* bupf = (const float*)d_in[24];
    const float* Wcf  = (const float*)d_in[25]; const float* bcf  = (const float*)d_in[26];
    float* outp = (float*)d_out;

    float *bufA, *bufB, *bufU, *bufY, *wt; double* stats; float2* mstat;
    cudaGetSymbolAddress((void**)&bufA, g_bufA);
    cudaGetSymbolAddress((void**)&bufB, g_bufB);
    cudaGetSymbolAddress((void**)&bufU, g_bufU);
    cudaGetSymbolAddress((void**)&bufY, g_bufY);
    cudaGetSymbolAddress((void**)&wt,   g_wt);
    cudaGetSymbolAddress((void**)&stats, g_stats);
    cudaGetSymbolAddress((void**)&mstat, g_mstat);

    float* Wt_up0 = wt;
    float* Wt_c0  = wt + 163840;
    float* Wt_up1 = wt + 245760;
    float* Wt_c1  = wt + 286720;
    float* Wt_up2 = wt + 307200;
    float* Wt_c2  = wt + 317440;
    float* Wt_upf = wt + 322560;
    float* Wt_cf  = wt + 323840;

    double* stats0 = stats;          // 2*128*2 = 512
    double* stats1 = stats + 512;    // 2*64*2  = 256
    double* stats2 = stats + 768;    // 2*32*2  = 128
    double* statsF = stats + 896;    // 2*8*2   = 32
    float2* mst0 = mstat;            // 256
    float2* mst1 = mstat + 256;      // 128
    float2* mst2 = mstat + 384;      // 64
    float2* mstF = mstat + 448;      // 16

    wtrans_all<<<1267, 256>>>(Wup0, Wc0, Wup1, Wc1, Wup2, Wc2, Wupf, Wcf, wt);
    zero_stats_all<<<4, 256>>>(stats);
    xpose<<<dim3(E0 / 32, 256 / 32, 2), dim3(32, 8)>>>(fe, bufA, E0, 256);

    // ---- Level 0 ----
    conv_f2<256, 128, 64, 8><<<dim3(E0 / 64, 2), 256>>>(bufA, gm0, Wt_up0, bup0, bufU, E0);
    unpool_skip<128><<<dim3(E1 / 32, 2), 256>>>(bufU, up0, skip0, bufY, E1, E0);
    conv_f2<128, 128, 64, 8><<<dim3(E1 / 64, 2), 256>>>(bufY, gm1, Wt_c0, bc0, bufB, E1);
    inorm_partial<128, 256><<<dim3(E1 / 256, 1, 2), 256>>>(bufB, E1, stats0);
    finalize_stats<<<1, 256>>>(stats0, mst0, 256, E1);
    inorm_apply<128><<<(2 * E1 * 128) / 256, 256>>>(bufB, E1, mst0);

    // ---- Level 1 ----
    conv_f2<128, 64, 128, 8><<<dim3(E1 / 128, 2), 256>>>(bufB, gm1, Wt_up1, bup1, bufU, E1);
    unpool_skip<64><<<dim3(E2 / 32, 2), 256>>>(bufU, up1, skip1, bufY, E2, E1);
    conv_f2<64, 64, 128, 8><<<dim3(E2 / 128, 2), 256>>>(bufY, gm2, Wt_c1, bc1, bufA, E2);
    inorm_partial<64, 512><<<dim3(E2 / 512, 1, 2), 256>>>(bufA, E2, stats1);
    finalize_stats<<<1, 128>>>(stats1, mst1, 128, E2);
    inorm_apply<64><<<(2 * E2 * 64) / 256, 256>>>(bufA, E2, mst1);

    // ---- Level 2 ----
    conv_f2<64, 32, 256, 4><<<dim3(E2 / 256, 2), 256>>>(bufA, gm2, Wt_up2, bup2, bufU, E2);
    unpool_skip<32><<<dim3(E3 / 32, 2), 256>>>(bufU, up2, skip2, bufY, E3, E2);
    conv_f2<32, 32, 256, 4><<<dim3(E3 / 256, 2), 256>>>(bufY, gm3, Wt_c2, bc2, bufB, E3);
    inorm_partial<32, 1024><<<dim3(E3 / 1024, 1, 2), 256>>>(bufB, E3, stats2);
    finalize_stats<<<1, 64>>>(stats2, mst2, 64, E3);
    inorm_apply<32><<<(2 * E3 * 32) / 256, 256>>>(bufB, E3, mst2);

    // ---- Final ----
    conv_small<32><<<dim3(E3 / 256, 2), 256>>>(bufB, gm3, Wt_upf, bupf, bufU, E3);
    conv_small<8><<<dim3(E3 / 256, 2), 256>>>(bufU, gm3, Wt_cf, bcf, bufY, E3);
    inorm_partial<8, 4096><<<dim3(E3 / 4096, 1, 2), 256>>>(bufY, E3, statsF);
    finalize_stats<<<1, 16>>>(statsF, mstF, 16, E3);
    inorm_apply_final<<<dim3(E3 / 32, 2), 256>>>(bufY, E3, mstF, outp);
}